// round 4
// baseline (speedup 1.0000x reference)
#include <cuda_runtime.h>
#include <math.h>

// Problem constants (fixed by setup_inputs)
#define U      128     // hidden units
#define ZD     512     // 4*U gate width
#define NC     10      // classes
#define NF     3       // input features
#define TT     1000    // timesteps
#define BB     256     // batch
#define G      4       // batch elements per block
#define NBLK   (BB/G)  // 64 blocks
#define NTHR   256

#define R_ON_   0.05f
#define ALPHA_  0.001f
#define LN_EPS_ 1e-3f

// ---- packed f32x2 helpers (Blackwell FFMA2: 2x fp32 FMA throughput) ----
__device__ __forceinline__ unsigned long long pack2(float a, float b) {
    unsigned long long r;
    asm("mov.b64 %0, {%1, %2};" : "=l"(r) : "f"(a), "f"(b));
    return r;
}
__device__ __forceinline__ float2 unpack2(unsigned long long v) {
    float2 r;
    asm("mov.b64 {%0, %1}, %2;" : "=f"(r.x), "=f"(r.y) : "l"(v));
    return r;
}
__device__ __forceinline__ void fma2p(unsigned long long& acc,
                                      unsigned long long w,
                                      unsigned long long h) {
    asm("fma.rn.f32x2 %0, %1, %2, %0;" : "+l"(acc) : "l"(w), "l"(h));
}

__device__ __forceinline__ float sigmoidf_(float x) { return 1.0f / (1.0f + expf(-x)); }

struct __align__(16) Smem {
    float z[2][G][ZD];          // per-K-slab partial gate pre-activations
    float h0[G][U], c0[G][U];
    float h1[G][U], c1[G][U];
    float hn[G][U];             // layernormed h0
    float Wx0[NF][ZD];
    float b0[ZD], b1[ZD];
    float tau0[U], s0[U], tau1[U], s1[U], gm[U], bt[U];
    float Wfc[U * NC];
    float bfc[NC];
    float x[2][G][NF];          // double-buffered inputs
    float tm[2][G];             // double-buffered times
    float red_s[G][4], red_q[G][4];
    float mu[G], rs[G];
    float logits[G][NC];
};

// Accumulate one 64-row K-slab of  hin[G][U] @ W[U][ZD]  into acc (4 cols/thread).
__device__ __forceinline__ void mv_accum(const float* __restrict__ W,
                                         const float* __restrict__ hin,
                                         int ks, int col,
                                         unsigned long long acc[G][2]) {
    const int kbase = ks * 64;
    #pragma unroll 4
    for (int k = 0; k < 64; ++k) {
        const int kk = kbase + k;
        float4 w = *reinterpret_cast<const float4*>(W + (size_t)kk * ZD + col);
        unsigned long long w01 = pack2(w.x, w.y);
        unsigned long long w23 = pack2(w.z, w.w);
        #pragma unroll
        for (int g = 0; g < G; ++g) {
            float hv = hin[g * U + kk];
            unsigned long long h2 = pack2(hv, hv);
            fma2p(acc[g][0], w01, h2);
            fma2p(acc[g][1], w23, h2);
        }
    }
}

// PhasedLSTM gate + time-gate update for one (batch, unit).
__device__ __forceinline__ void plstm_gate(const float* __restrict__ z0,
                                           const float* __restrict__ z1,
                                           int u, float tcur, float tau, float s,
                                           float& h, float& c) {
    float zi = z0[u]         + z1[u];
    float zf = z0[u + 128]   + z1[u + 128];
    float zg = z0[u + 256]   + z1[u + 256];
    float zo = z0[u + 384]   + z1[u + 384];
    float ch = sigmoidf_(zf) * c + sigmoidf_(zi) * tanhf(zg);
    float hh = sigmoidf_(zo) * tanhf(ch);

    float d = tcur - s;
    float m = fmodf(d, tau);          // exact, matches lax.rem
    if (m < 0.0f) m += tau;           // python-style mod (sign of divisor)
    float phi = m / tau;
    float kgate;
    if (phi < 0.5f * R_ON_)      kgate = 2.0f * phi / R_ON_;
    else if (phi < R_ON_)        kgate = 2.0f - 2.0f * phi / R_ON_;
    else                         kgate = ALPHA_ * phi;

    h = kgate * hh + (1.0f - kgate) * h;
    c = kgate * ch + (1.0f - kgate) * c;
}

__global__ void __launch_bounds__(NTHR, 1)
plstm_kernel(const float* __restrict__ inputs, const float* __restrict__ times,
             const float* __restrict__ gWx0, const float* __restrict__ gWh0,
             const float* __restrict__ gb0,  const float* __restrict__ gtau0,
             const float* __restrict__ gs0,  const float* __restrict__ gWx1,
             const float* __restrict__ gWh1, const float* __restrict__ gb1,
             const float* __restrict__ gtau1,const float* __restrict__ gs1,
             const float* __restrict__ ggamma,const float* __restrict__ gbeta,
             const float* __restrict__ gWfc, const float* __restrict__ gbfc,
             float* __restrict__ out) {
    __shared__ Smem sm;
    const int tid    = threadIdx.x;
    const int bstart = blockIdx.x * G;

    // ---- one-time SMEM setup ----
    for (int i = tid; i < G * U; i += NTHR) {
        (&sm.h0[0][0])[i] = 0.0f; (&sm.c0[0][0])[i] = 0.0f;
        (&sm.h1[0][0])[i] = 0.0f; (&sm.c1[0][0])[i] = 0.0f;
    }
    for (int i = tid; i < NF * ZD; i += NTHR) (&sm.Wx0[0][0])[i] = gWx0[i];
    for (int i = tid; i < ZD; i += NTHR) { sm.b0[i] = gb0[i]; sm.b1[i] = gb1[i]; }
    for (int i = tid; i < U;  i += NTHR) {
        sm.tau0[i] = gtau0[i]; sm.s0[i] = gs0[i];
        sm.tau1[i] = gtau1[i]; sm.s1[i] = gs1[i];
        sm.gm[i]   = ggamma[i]; sm.bt[i] = gbeta[i];
    }
    for (int i = tid; i < U * NC; i += NTHR) sm.Wfc[i] = gWfc[i];
    if (tid < NC) sm.bfc[tid] = gbfc[tid];
    if (tid < G)  sm.tm[0][tid] = times[(size_t)(bstart + tid) * TT];
    if (tid < G * NF) {
        int g = tid / NF, f = tid - g * NF;
        sm.x[0][g][f] = inputs[((size_t)(bstart + g) * TT) * NF + f];
    }
    __syncthreads();

    const int ks   = tid >> 7;          // K-slab (0/1)
    const int col  = (tid & 127) * 4;   // 4 output columns of 512
    const int gg   = tid >> 7;          // gate-phase batch (items gg and gg+2)
    const int uu   = tid & 127;
    const int lane = tid & 31;
    const int wsub = (tid >> 5) & 3;

    for (int t = 0; t < TT; ++t) {
        const int buf = t & 1;

        // ================= layer 0: z = x@Wx0 + h0@Wh0 + b0 =================
        unsigned long long acc[G][2];
        if (ks == 0) {
            #pragma unroll
            for (int g = 0; g < G; ++g) {
                float xa = sm.x[buf][g][0], xb = sm.x[buf][g][1], xc = sm.x[buf][g][2];
                float a[4];
                #pragma unroll
                for (int j = 0; j < 4; ++j)
                    a[j] = sm.b0[col + j] + xa * sm.Wx0[0][col + j]
                                          + xb * sm.Wx0[1][col + j]
                                          + xc * sm.Wx0[2][col + j];
                acc[g][0] = pack2(a[0], a[1]);
                acc[g][1] = pack2(a[2], a[3]);
            }
        } else {
            #pragma unroll
            for (int g = 0; g < G; ++g) { acc[g][0] = 0ull; acc[g][1] = 0ull; }
        }
        mv_accum(gWh0, &sm.h0[0][0], ks, col, acc);
        #pragma unroll
        for (int g = 0; g < G; ++g) {
            float2 p = unpack2(acc[g][0]), q = unpack2(acc[g][1]);
            *reinterpret_cast<float4*>(&sm.z[ks][g][col]) = make_float4(p.x, p.y, q.x, q.y);
        }
        __syncthreads();

        // ---- gates layer 0 (+ LayerNorm statistics) ----
        float hA = sm.h0[gg][uu],     cA = sm.c0[gg][uu];
        float hB = sm.h0[gg + 2][uu], cB = sm.c0[gg + 2][uu];
        plstm_gate(&sm.z[0][gg][0],     &sm.z[1][gg][0],     uu, sm.tm[buf][gg],
                   sm.tau0[uu], sm.s0[uu], hA, cA);
        plstm_gate(&sm.z[0][gg + 2][0], &sm.z[1][gg + 2][0], uu, sm.tm[buf][gg + 2],
                   sm.tau0[uu], sm.s0[uu], hB, cB);
        sm.h0[gg][uu] = hA;     sm.c0[gg][uu] = cA;
        sm.h0[gg + 2][uu] = hB; sm.c0[gg + 2][uu] = cB;

        float sA = hA, qA = hA * hA, sB = hB, qB = hB * hB;
        #pragma unroll
        for (int o = 16; o; o >>= 1) {
            sA += __shfl_xor_sync(0xffffffffu, sA, o);
            qA += __shfl_xor_sync(0xffffffffu, qA, o);
            sB += __shfl_xor_sync(0xffffffffu, sB, o);
            qB += __shfl_xor_sync(0xffffffffu, qB, o);
        }
        if (lane == 0) {
            sm.red_s[gg][wsub] = sA;     sm.red_q[gg][wsub] = qA;
            sm.red_s[gg + 2][wsub] = sB; sm.red_q[gg + 2][wsub] = qB;
        }
        __syncthreads();
        if (tid < G) {
            float s4 = sm.red_s[tid][0] + sm.red_s[tid][1] + sm.red_s[tid][2] + sm.red_s[tid][3];
            float q4 = sm.red_q[tid][0] + sm.red_q[tid][1] + sm.red_q[tid][2] + sm.red_q[tid][3];
            float mu  = s4 * (1.0f / U);
            float var = fmaxf(q4 * (1.0f / U) - mu * mu, 0.0f);
            sm.mu[tid] = mu;
            sm.rs[tid] = rsqrtf(var + LN_EPS_);
        }
        __syncthreads();
        sm.hn[gg][uu]     = sm.gm[uu] * (hA - sm.mu[gg])     * sm.rs[gg]     + sm.bt[uu];
        sm.hn[gg + 2][uu] = sm.gm[uu] * (hB - sm.mu[gg + 2]) * sm.rs[gg + 2] + sm.bt[uu];
        __syncthreads();

        // ---- prefetch next step's x/t into the other buffer ----
        if (t + 1 < TT) {
            int nb = buf ^ 1;
            if (tid < G) sm.tm[nb][tid] = times[(size_t)(bstart + tid) * TT + (t + 1)];
            if (tid < G * NF) {
                int g = tid / NF, f = tid - g * NF;
                sm.x[nb][g][f] = inputs[((size_t)(bstart + g) * TT + (t + 1)) * NF + f];
            }
        }

        // ================= layer 1: z = hn@Wx1 + h1@Wh1 + b1 =================
        if (ks == 0) {
            #pragma unroll
            for (int g = 0; g < G; ++g) {
                acc[g][0] = pack2(sm.b1[col + 0], sm.b1[col + 1]);
                acc[g][1] = pack2(sm.b1[col + 2], sm.b1[col + 3]);
            }
        } else {
            #pragma unroll
            for (int g = 0; g < G; ++g) { acc[g][0] = 0ull; acc[g][1] = 0ull; }
        }
        mv_accum(gWx1, &sm.hn[0][0], ks, col, acc);
        mv_accum(gWh1, &sm.h1[0][0], ks, col, acc);
        #pragma unroll
        for (int g = 0; g < G; ++g) {
            float2 p = unpack2(acc[g][0]), q = unpack2(acc[g][1]);
            *reinterpret_cast<float4*>(&sm.z[ks][g][col]) = make_float4(p.x, p.y, q.x, q.y);
        }
        __syncthreads();

        // ---- gates layer 1 ----
        float h1A = sm.h1[gg][uu],     c1A = sm.c1[gg][uu];
        float h1B = sm.h1[gg + 2][uu], c1B = sm.c1[gg + 2][uu];
        plstm_gate(&sm.z[0][gg][0],     &sm.z[1][gg][0],     uu, sm.tm[buf][gg],
                   sm.tau1[uu], sm.s1[uu], h1A, c1A);
        plstm_gate(&sm.z[0][gg + 2][0], &sm.z[1][gg + 2][0], uu, sm.tm[buf][gg + 2],
                   sm.tau1[uu], sm.s1[uu], h1B, c1B);
        sm.h1[gg][uu] = h1A;     sm.c1[gg][uu] = c1A;
        sm.h1[gg + 2][uu] = h1B; sm.c1[gg + 2][uu] = c1B;
        __syncthreads();

        // ================= output: softmax(h1 @ Wfc + bfc) =================
        if (tid < 160) {                       // 40 (g,c) pairs x 4 threads
            int pair = tid >> 2, sub = tid & 3;
            int g = pair / NC, c = pair - g * NC;
            float a = 0.0f;
            #pragma unroll
            for (int i = 0; i < 32; ++i) {
                int u = sub + 4 * i;
                a += sm.h1[g][u] * sm.Wfc[u * NC + c];
            }
            a += __shfl_xor_sync(0xffffffffu, a, 1);
            a += __shfl_xor_sync(0xffffffffu, a, 2);
            if (sub == 0) sm.logits[g][c] = a + sm.bfc[c];
        }
        __syncthreads();
        if (tid < G) {
            float mx = -1e30f;
            #pragma unroll
            for (int c = 0; c < NC; ++c) mx = fmaxf(mx, sm.logits[tid][c]);
            float e[NC]; float s = 0.0f;
            #pragma unroll
            for (int c = 0; c < NC; ++c) { e[c] = expf(sm.logits[tid][c] - mx); s += e[c]; }
            float inv = 1.0f / s;
            float* op = out + ((size_t)(bstart + tid) * TT + t) * NC;
            #pragma unroll
            for (int c = 0; c < NC; ++c) op[c] = e[c] * inv;
        }
        // No trailing barrier needed: every SMEM buffer written early in the next
        // iteration is separated from this iteration's readers by >=1 __syncthreads().
    }
}

extern "C" void kernel_launch(void* const* d_in, const int* in_sizes, int n_in,
                              void* d_out, int out_size) {
    const float* inputs = (const float*)d_in[0];
    const float* times  = (const float*)d_in[1];
    const float* Wx0    = (const float*)d_in[2];
    const float* Wh0    = (const float*)d_in[3];
    const float* b0     = (const float*)d_in[4];
    const float* tau0   = (const float*)d_in[5];
    const float* s0     = (const float*)d_in[6];
    const float* Wx1    = (const float*)d_in[7];
    const float* Wh1    = (const float*)d_in[8];
    const float* b1     = (const float*)d_in[9];
    const float* tau1   = (const float*)d_in[10];
    const float* s1     = (const float*)d_in[11];
    const float* gamma  = (const float*)d_in[12];
    const float* beta   = (const float*)d_in[13];
    const float* Wfc    = (const float*)d_in[14];
    const float* bfc    = (const float*)d_in[15];

    plstm_kernel<<<NBLK, NTHR>>>(inputs, times, Wx0, Wh0, b0, tau0, s0,
                                 Wx1, Wh1, b1, tau1, s1, gamma, beta,
                                 Wfc, bfc, (float*)d_out);
}

// round 5
// speedup vs baseline: 1.0043x; 1.0043x over previous
#include <cuda_runtime.h>
#include <math.h>

// Problem constants (fixed by setup_inputs)
#define U      128     // hidden units
#define ZD     512     // 4*U gate width
#define NC     10      // classes
#define NF     3       // input features
#define TT     1000    // timesteps
#define BB     256     // batch
#define G      4       // batch elements per block
#define NBLK   (BB/G)  // 64 blocks
#define NTHR   256

#define R_ON_   0.05f
#define ALPHA_  0.001f
#define LN_EPS_ 1e-3f

// ---- packed f32x2 helpers (Blackwell FFMA2: 2x fp32 FMA throughput) ----
__device__ __forceinline__ unsigned long long pack2(float a, float b) {
    unsigned long long r;
    asm("mov.b64 %0, {%1, %2};" : "=l"(r) : "f"(a), "f"(b));
    return r;
}
__device__ __forceinline__ float2 unpack2(unsigned long long v) {
    float2 r;
    asm("mov.b64 {%0, %1}, %2;" : "=f"(r.x), "=f"(r.y) : "l"(v));
    return r;
}
__device__ __forceinline__ void fma2p(unsigned long long& acc,
                                      unsigned long long w,
                                      unsigned long long h) {
    asm("fma.rn.f32x2 %0, %1, %2, %0;" : "+l"(acc) : "l"(w), "l"(h));
}

__device__ __forceinline__ float sigmoidf_(float x) { return 1.0f / (1.0f + expf(-x)); }

struct __align__(16) Smem {
    float z[2][G][ZD];          // per-K-slab partial gate pre-activations
    float h0[G][U], c0[G][U];
    float h1[G][U], c1[G][U];
    float hn[G][U];             // layernormed h0
    float Wx0[NF][ZD];
    float b0[ZD], b1[ZD];
    float tau0[U], s0[U], tau1[U], s1[U], gm[U], bt[U];
    float Wfc[U * NC];
    float bfc[NC];
    float x[2][G][NF];          // double-buffered inputs
    float tm[2][G];             // double-buffered times
    float red_s[G][4], red_q[G][4];
    float mu[G], rs[G];
    float logits[G][NC];
};

// Accumulate one 64-row K-slab of  hin[G][U] @ W[U][ZD]  into acc (4 cols/thread).
__device__ __forceinline__ void mv_accum(const float* __restrict__ W,
                                         const float* __restrict__ hin,
                                         int ks, int col,
                                         unsigned long long acc[G][2]) {
    const int kbase = ks * 64;
    #pragma unroll 4
    for (int k = 0; k < 64; ++k) {
        const int kk = kbase + k;
        float4 w = *reinterpret_cast<const float4*>(W + (size_t)kk * ZD + col);
        unsigned long long w01 = pack2(w.x, w.y);
        unsigned long long w23 = pack2(w.z, w.w);
        #pragma unroll
        for (int g = 0; g < G; ++g) {
            float hv = hin[g * U + kk];
            unsigned long long h2 = pack2(hv, hv);
            fma2p(acc[g][0], w01, h2);
            fma2p(acc[g][1], w23, h2);
        }
    }
}

// PhasedLSTM gate + time-gate update for one (batch, unit).
__device__ __forceinline__ void plstm_gate(const float* __restrict__ z0,
                                           const float* __restrict__ z1,
                                           int u, float tcur, float tau, float s,
                                           float& h, float& c) {
    float zi = z0[u]         + z1[u];
    float zf = z0[u + 128]   + z1[u + 128];
    float zg = z0[u + 256]   + z1[u + 256];
    float zo = z0[u + 384]   + z1[u + 384];
    float ch = sigmoidf_(zf) * c + sigmoidf_(zi) * tanhf(zg);
    float hh = sigmoidf_(zo) * tanhf(ch);

    float d = tcur - s;
    float m = fmodf(d, tau);          // exact, matches lax.rem
    if (m < 0.0f) m += tau;           // python-style mod (sign of divisor)
    float phi = m / tau;
    float kgate;
    if (phi < 0.5f * R_ON_)      kgate = 2.0f * phi / R_ON_;
    else if (phi < R_ON_)        kgate = 2.0f - 2.0f * phi / R_ON_;
    else                         kgate = ALPHA_ * phi;

    h = kgate * hh + (1.0f - kgate) * h;
    c = kgate * ch + (1.0f - kgate) * c;
}

__global__ void __launch_bounds__(NTHR, 1)
plstm_kernel(const float* __restrict__ inputs, const float* __restrict__ times,
             const float* __restrict__ gWx0, const float* __restrict__ gWh0,
             const float* __restrict__ gb0,  const float* __restrict__ gtau0,
             const float* __restrict__ gs0,  const float* __restrict__ gWx1,
             const float* __restrict__ gWh1, const float* __restrict__ gb1,
             const float* __restrict__ gtau1,const float* __restrict__ gs1,
             const float* __restrict__ ggamma,const float* __restrict__ gbeta,
             const float* __restrict__ gWfc, const float* __restrict__ gbfc,
             float* __restrict__ out) {
    __shared__ Smem sm;
    const int tid    = threadIdx.x;
    const int bstart = blockIdx.x * G;

    // ---- one-time SMEM setup ----
    for (int i = tid; i < G * U; i += NTHR) {
        (&sm.h0[0][0])[i] = 0.0f; (&sm.c0[0][0])[i] = 0.0f;
        (&sm.h1[0][0])[i] = 0.0f; (&sm.c1[0][0])[i] = 0.0f;
    }
    for (int i = tid; i < NF * ZD; i += NTHR) (&sm.Wx0[0][0])[i] = gWx0[i];
    for (int i = tid; i < ZD; i += NTHR) { sm.b0[i] = gb0[i]; sm.b1[i] = gb1[i]; }
    for (int i = tid; i < U;  i += NTHR) {
        sm.tau0[i] = gtau0[i]; sm.s0[i] = gs0[i];
        sm.tau1[i] = gtau1[i]; sm.s1[i] = gs1[i];
        sm.gm[i]   = ggamma[i]; sm.bt[i] = gbeta[i];
    }
    for (int i = tid; i < U * NC; i += NTHR) sm.Wfc[i] = gWfc[i];
    if (tid < NC) sm.bfc[tid] = gbfc[tid];
    if (tid < G)  sm.tm[0][tid] = times[(size_t)(bstart + tid) * TT];
    if (tid < G * NF) {
        int g = tid / NF, f = tid - g * NF;
        sm.x[0][g][f] = inputs[((size_t)(bstart + g) * TT) * NF + f];
    }
    __syncthreads();

    const int ks   = tid >> 7;          // K-slab (0/1)
    const int col  = (tid & 127) * 4;   // 4 output columns of 512
    const int gg   = tid >> 7;          // gate-phase batch (items gg and gg+2)
    const int uu   = tid & 127;
    const int lane = tid & 31;
    const int wsub = (tid >> 5) & 3;

    for (int t = 0; t < TT; ++t) {
        const int buf = t & 1;

        // ================= layer 0: z = x@Wx0 + h0@Wh0 + b0 =================
        unsigned long long acc[G][2];
        if (ks == 0) {
            #pragma unroll
            for (int g = 0; g < G; ++g) {
                float xa = sm.x[buf][g][0], xb = sm.x[buf][g][1], xc = sm.x[buf][g][2];
                float a[4];
                #pragma unroll
                for (int j = 0; j < 4; ++j)
                    a[j] = sm.b0[col + j] + xa * sm.Wx0[0][col + j]
                                          + xb * sm.Wx0[1][col + j]
                                          + xc * sm.Wx0[2][col + j];
                acc[g][0] = pack2(a[0], a[1]);
                acc[g][1] = pack2(a[2], a[3]);
            }
        } else {
            #pragma unroll
            for (int g = 0; g < G; ++g) { acc[g][0] = 0ull; acc[g][1] = 0ull; }
        }
        mv_accum(gWh0, &sm.h0[0][0], ks, col, acc);
        #pragma unroll
        for (int g = 0; g < G; ++g) {
            float2 p = unpack2(acc[g][0]), q = unpack2(acc[g][1]);
            *reinterpret_cast<float4*>(&sm.z[ks][g][col]) = make_float4(p.x, p.y, q.x, q.y);
        }
        __syncthreads();

        // ---- gates layer 0 (+ LayerNorm statistics) ----
        float hA = sm.h0[gg][uu],     cA = sm.c0[gg][uu];
        float hB = sm.h0[gg + 2][uu], cB = sm.c0[gg + 2][uu];
        plstm_gate(&sm.z[0][gg][0],     &sm.z[1][gg][0],     uu, sm.tm[buf][gg],
                   sm.tau0[uu], sm.s0[uu], hA, cA);
        plstm_gate(&sm.z[0][gg + 2][0], &sm.z[1][gg + 2][0], uu, sm.tm[buf][gg + 2],
                   sm.tau0[uu], sm.s0[uu], hB, cB);
        sm.h0[gg][uu] = hA;     sm.c0[gg][uu] = cA;
        sm.h0[gg + 2][uu] = hB; sm.c0[gg + 2][uu] = cB;

        float sA = hA, qA = hA * hA, sB = hB, qB = hB * hB;
        #pragma unroll
        for (int o = 16; o; o >>= 1) {
            sA += __shfl_xor_sync(0xffffffffu, sA, o);
            qA += __shfl_xor_sync(0xffffffffu, qA, o);
            sB += __shfl_xor_sync(0xffffffffu, sB, o);
            qB += __shfl_xor_sync(0xffffffffu, qB, o);
        }
        if (lane == 0) {
            sm.red_s[gg][wsub] = sA;     sm.red_q[gg][wsub] = qA;
            sm.red_s[gg + 2][wsub] = sB; sm.red_q[gg + 2][wsub] = qB;
        }
        __syncthreads();
        if (tid < G) {
            float s4 = sm.red_s[tid][0] + sm.red_s[tid][1] + sm.red_s[tid][2] + sm.red_s[tid][3];
            float q4 = sm.red_q[tid][0] + sm.red_q[tid][1] + sm.red_q[tid][2] + sm.red_q[tid][3];
            float mu  = s4 * (1.0f / U);
            float var = fmaxf(q4 * (1.0f / U) - mu * mu, 0.0f);
            sm.mu[tid] = mu;
            sm.rs[tid] = rsqrtf(var + LN_EPS_);
        }
        __syncthreads();
        sm.hn[gg][uu]     = sm.gm[uu] * (hA - sm.mu[gg])     * sm.rs[gg]     + sm.bt[uu];
        sm.hn[gg + 2][uu] = sm.gm[uu] * (hB - sm.mu[gg + 2]) * sm.rs[gg + 2] + sm.bt[uu];
        __syncthreads();

        // ---- prefetch next step's x/t into the other buffer ----
        if (t + 1 < TT) {
            int nb = buf ^ 1;
            if (tid < G) sm.tm[nb][tid] = times[(size_t)(bstart + tid) * TT + (t + 1)];
            if (tid < G * NF) {
                int g = tid / NF, f = tid - g * NF;
                sm.x[nb][g][f] = inputs[((size_t)(bstart + g) * TT + (t + 1)) * NF + f];
            }
        }

        // ================= layer 1: z = hn@Wx1 + h1@Wh1 + b1 =================
        if (ks == 0) {
            #pragma unroll
            for (int g = 0; g < G; ++g) {
                acc[g][0] = pack2(sm.b1[col + 0], sm.b1[col + 1]);
                acc[g][1] = pack2(sm.b1[col + 2], sm.b1[col + 3]);
            }
        } else {
            #pragma unroll
            for (int g = 0; g < G; ++g) { acc[g][0] = 0ull; acc[g][1] = 0ull; }
        }
        mv_accum(gWx1, &sm.hn[0][0], ks, col, acc);
        mv_accum(gWh1, &sm.h1[0][0], ks, col, acc);
        #pragma unroll
        for (int g = 0; g < G; ++g) {
            float2 p = unpack2(acc[g][0]), q = unpack2(acc[g][1]);
            *reinterpret_cast<float4*>(&sm.z[ks][g][col]) = make_float4(p.x, p.y, q.x, q.y);
        }
        __syncthreads();

        // ---- gates layer 1 ----
        float h1A = sm.h1[gg][uu],     c1A = sm.c1[gg][uu];
        float h1B = sm.h1[gg + 2][uu], c1B = sm.c1[gg + 2][uu];
        plstm_gate(&sm.z[0][gg][0],     &sm.z[1][gg][0],     uu, sm.tm[buf][gg],
                   sm.tau1[uu], sm.s1[uu], h1A, c1A);
        plstm_gate(&sm.z[0][gg + 2][0], &sm.z[1][gg + 2][0], uu, sm.tm[buf][gg + 2],
                   sm.tau1[uu], sm.s1[uu], h1B, c1B);
        sm.h1[gg][uu] = h1A;     sm.c1[gg][uu] = c1A;
        sm.h1[gg + 2][uu] = h1B; sm.c1[gg + 2][uu] = c1B;
        __syncthreads();

        // ================= output: softmax(h1 @ Wfc + bfc) =================
        if (tid < 160) {                       // 40 (g,c) pairs x 4 threads
            int pair = tid >> 2, sub = tid & 3;
            int g = pair / NC, c = pair - g * NC;
            float a = 0.0f;
            #pragma unroll
            for (int i = 0; i < 32; ++i) {
                int u = sub + 4 * i;
                a += sm.h1[g][u] * sm.Wfc[u * NC + c];
            }
            a += __shfl_xor_sync(0xffffffffu, a, 1);
            a += __shfl_xor_sync(0xffffffffu, a, 2);
            if (sub == 0) sm.logits[g][c] = a + sm.bfc[c];
        }
        __syncthreads();
        if (tid < G) {
            float mx = -1e30f;
            #pragma unroll
            for (int c = 0; c < NC; ++c) mx = fmaxf(mx, sm.logits[tid][c]);
            float e[NC]; float s = 0.0f;
            #pragma unroll
            for (int c = 0; c < NC; ++c) { e[c] = expf(sm.logits[tid][c] - mx); s += e[c]; }
            float inv = 1.0f / s;
            float* op = out + ((size_t)(bstart + tid) * TT + t) * NC;
            #pragma unroll
            for (int c = 0; c < NC; ++c) op[c] = e[c] * inv;
        }
        // No trailing barrier needed: every SMEM buffer written early in the next
        // iteration is separated from this iteration's readers by >=1 __syncthreads().
    }
}

extern "C" void kernel_launch(void* const* d_in, const int* in_sizes, int n_in,
                              void* d_out, int out_size) {
    const float* inputs = (const float*)d_in[0];
    const float* times  = (const float*)d_in[1];
    const float* Wx0    = (const float*)d_in[2];
    const float* Wh0    = (const float*)d_in[3];
    const float* b0     = (const float*)d_in[4];
    const float* tau0   = (const float*)d_in[5];
    const float* s0     = (const float*)d_in[6];
    const float* Wx1    = (const float*)d_in[7];
    const float* Wh1    = (const float*)d_in[8];
    const float* b1     = (const float*)d_in[9];
    const float* tau1   = (const float*)d_in[10];
    const float* s1     = (const float*)d_in[11];
    const float* gamma  = (const float*)d_in[12];
    const float* beta   = (const float*)d_in[13];
    const float* Wfc    = (const float*)d_in[14];
    const float* bfc    = (const float*)d_in[15];

    plstm_kernel<<<NBLK, NTHR>>>(inputs, times, Wx0, Wh0, b0, tau0, s0,
                                 Wx1, Wh1, b1, tau1, s1, gamma, beta,
                                 Wfc, bfc, (float*)d_out);
}

// round 6
// speedup vs baseline: 1.0047x; 1.0004x over previous
#include <cuda_runtime.h>
#include <math.h>

// Problem constants (fixed by setup_inputs)
#define U      128     // hidden units
#define ZD     512     // 4*U gate width
#define NC     10      // classes
#define NF     3       // input features
#define TT     1000    // timesteps
#define BB     256     // batch
#define G      4       // batch elements per block
#define NBLK   (BB/G)  // 64 blocks
#define NTHR   256

#define R_ON_   0.05f
#define ALPHA_  0.001f
#define LN_EPS_ 1e-3f

// ---- packed f32x2 helpers (Blackwell FFMA2: 2x fp32 FMA throughput) ----
__device__ __forceinline__ unsigned long long pack2(float a, float b) {
    unsigned long long r;
    asm("mov.b64 %0, {%1, %2};" : "=l"(r) : "f"(a), "f"(b));
    return r;
}
__device__ __forceinline__ float2 unpack2(unsigned long long v) {
    float2 r;
    asm("mov.b64 {%0, %1}, %2;" : "=f"(r.x), "=f"(r.y) : "l"(v));
    return r;
}
__device__ __forceinline__ void fma2p(unsigned long long& acc,
                                      unsigned long long w,
                                      unsigned long long h) {
    asm("fma.rn.f32x2 %0, %1, %2, %0;" : "+l"(acc) : "l"(w), "l"(h));
}

__device__ __forceinline__ float sigmoidf_(float x) { return 1.0f / (1.0f + expf(-x)); }

struct __align__(16) Smem {
    float z[2][G][ZD];          // per-K-slab partial gate pre-activations
    float h0[G][U], c0[G][U];
    float h1[G][U], c1[G][U];
    float hn[G][U];             // layernormed h0
    float Wx0[NF][ZD];
    float b0[ZD], b1[ZD];
    float tau0[U], s0[U], tau1[U], s1[U], gm[U], bt[U];
    float Wfc[U * NC];
    float bfc[NC];
    float x[2][G][NF];          // double-buffered inputs
    float tm[2][G];             // double-buffered times
    float red_s[G][4], red_q[G][4];
    float mu[G], rs[G];
    float logits[G][NC];
};

// Accumulate one 64-row K-slab of  hin[G][U] @ W[U][ZD]  into acc (4 cols/thread).
__device__ __forceinline__ void mv_accum(const float* __restrict__ W,
                                         const float* __restrict__ hin,
                                         int ks, int col,
                                         unsigned long long acc[G][2]) {
    const int kbase = ks * 64;
    #pragma unroll 4
    for (int k = 0; k < 64; ++k) {
        const int kk = kbase + k;
        float4 w = *reinterpret_cast<const float4*>(W + (size_t)kk * ZD + col);
        unsigned long long w01 = pack2(w.x, w.y);
        unsigned long long w23 = pack2(w.z, w.w);
        #pragma unroll
        for (int g = 0; g < G; ++g) {
            float hv = hin[g * U + kk];
            unsigned long long h2 = pack2(hv, hv);
            fma2p(acc[g][0], w01, h2);
            fma2p(acc[g][1], w23, h2);
        }
    }
}

// PhasedLSTM gate + time-gate update for one (batch, unit).
__device__ __forceinline__ void plstm_gate(const float* __restrict__ z0,
                                           const float* __restrict__ z1,
                                           int u, float tcur, float tau, float s,
                                           float& h, float& c) {
    float zi = z0[u]         + z1[u];
    float zf = z0[u + 128]   + z1[u + 128];
    float zg = z0[u + 256]   + z1[u + 256];
    float zo = z0[u + 384]   + z1[u + 384];
    float ch = sigmoidf_(zf) * c + sigmoidf_(zi) * tanhf(zg);
    float hh = sigmoidf_(zo) * tanhf(ch);

    float d = tcur - s;
    float m = fmodf(d, tau);          // exact, matches lax.rem
    if (m < 0.0f) m += tau;           // python-style mod (sign of divisor)
    float phi = m / tau;
    float kgate;
    if (phi < 0.5f * R_ON_)      kgate = 2.0f * phi / R_ON_;
    else if (phi < R_ON_)        kgate = 2.0f - 2.0f * phi / R_ON_;
    else                         kgate = ALPHA_ * phi;

    h = kgate * hh + (1.0f - kgate) * h;
    c = kgate * ch + (1.0f - kgate) * c;
}

__global__ void __launch_bounds__(NTHR, 1)
plstm_kernel(const float* __restrict__ inputs, const float* __restrict__ times,
             const float* __restrict__ gWx0, const float* __restrict__ gWh0,
             const float* __restrict__ gb0,  const float* __restrict__ gtau0,
             const float* __restrict__ gs0,  const float* __restrict__ gWx1,
             const float* __restrict__ gWh1, const float* __restrict__ gb1,
             const float* __restrict__ gtau1,const float* __restrict__ gs1,
             const float* __restrict__ ggamma,const float* __restrict__ gbeta,
             const float* __restrict__ gWfc, const float* __restrict__ gbfc,
             float* __restrict__ out) {
    __shared__ Smem sm;
    const int tid    = threadIdx.x;
    const int bstart = blockIdx.x * G;

    // ---- one-time SMEM setup ----
    for (int i = tid; i < G * U; i += NTHR) {
        (&sm.h0[0][0])[i] = 0.0f; (&sm.c0[0][0])[i] = 0.0f;
        (&sm.h1[0][0])[i] = 0.0f; (&sm.c1[0][0])[i] = 0.0f;
    }
    for (int i = tid; i < NF * ZD; i += NTHR) (&sm.Wx0[0][0])[i] = gWx0[i];
    for (int i = tid; i < ZD; i += NTHR) { sm.b0[i] = gb0[i]; sm.b1[i] = gb1[i]; }
    for (int i = tid; i < U;  i += NTHR) {
        sm.tau0[i] = gtau0[i]; sm.s0[i] = gs0[i];
        sm.tau1[i] = gtau1[i]; sm.s1[i] = gs1[i];
        sm.gm[i]   = ggamma[i]; sm.bt[i] = gbeta[i];
    }
    for (int i = tid; i < U * NC; i += NTHR) sm.Wfc[i] = gWfc[i];
    if (tid < NC) sm.bfc[tid] = gbfc[tid];
    if (tid < G)  sm.tm[0][tid] = times[(size_t)(bstart + tid) * TT];
    if (tid < G * NF) {
        int g = tid / NF, f = tid - g * NF;
        sm.x[0][g][f] = inputs[((size_t)(bstart + g) * TT) * NF + f];
    }
    __syncthreads();

    const int ks   = tid >> 7;          // K-slab (0/1)
    const int col  = (tid & 127) * 4;   // 4 output columns of 512
    const int gg   = tid >> 7;          // gate-phase batch (items gg and gg+2)
    const int uu   = tid & 127;
    const int lane = tid & 31;
    const int wsub = (tid >> 5) & 3;

    for (int t = 0; t < TT; ++t) {
        const int buf = t & 1;

        // ================= layer 0: z = x@Wx0 + h0@Wh0 + b0 =================
        unsigned long long acc[G][2];
        if (ks == 0) {
            #pragma unroll
            for (int g = 0; g < G; ++g) {
                float xa = sm.x[buf][g][0], xb = sm.x[buf][g][1], xc = sm.x[buf][g][2];
                float a[4];
                #pragma unroll
                for (int j = 0; j < 4; ++j)
                    a[j] = sm.b0[col + j] + xa * sm.Wx0[0][col + j]
                                          + xb * sm.Wx0[1][col + j]
                                          + xc * sm.Wx0[2][col + j];
                acc[g][0] = pack2(a[0], a[1]);
                acc[g][1] = pack2(a[2], a[3]);
            }
        } else {
            #pragma unroll
            for (int g = 0; g < G; ++g) { acc[g][0] = 0ull; acc[g][1] = 0ull; }
        }
        mv_accum(gWh0, &sm.h0[0][0], ks, col, acc);
        #pragma unroll
        for (int g = 0; g < G; ++g) {
            float2 p = unpack2(acc[g][0]), q = unpack2(acc[g][1]);
            *reinterpret_cast<float4*>(&sm.z[ks][g][col]) = make_float4(p.x, p.y, q.x, q.y);
        }
        __syncthreads();

        // ---- gates layer 0 (+ LayerNorm statistics) ----
        float hA = sm.h0[gg][uu],     cA = sm.c0[gg][uu];
        float hB = sm.h0[gg + 2][uu], cB = sm.c0[gg + 2][uu];
        plstm_gate(&sm.z[0][gg][0],     &sm.z[1][gg][0],     uu, sm.tm[buf][gg],
                   sm.tau0[uu], sm.s0[uu], hA, cA);
        plstm_gate(&sm.z[0][gg + 2][0], &sm.z[1][gg + 2][0], uu, sm.tm[buf][gg + 2],
                   sm.tau0[uu], sm.s0[uu], hB, cB);
        sm.h0[gg][uu] = hA;     sm.c0[gg][uu] = cA;
        sm.h0[gg + 2][uu] = hB; sm.c0[gg + 2][uu] = cB;

        float sA = hA, qA = hA * hA, sB = hB, qB = hB * hB;
        #pragma unroll
        for (int o = 16; o; o >>= 1) {
            sA += __shfl_xor_sync(0xffffffffu, sA, o);
            qA += __shfl_xor_sync(0xffffffffu, qA, o);
            sB += __shfl_xor_sync(0xffffffffu, sB, o);
            qB += __shfl_xor_sync(0xffffffffu, qB, o);
        }
        if (lane == 0) {
            sm.red_s[gg][wsub] = sA;     sm.red_q[gg][wsub] = qA;
            sm.red_s[gg + 2][wsub] = sB; sm.red_q[gg + 2][wsub] = qB;
        }
        __syncthreads();
        if (tid < G) {
            float s4 = sm.red_s[tid][0] + sm.red_s[tid][1] + sm.red_s[tid][2] + sm.red_s[tid][3];
            float q4 = sm.red_q[tid][0] + sm.red_q[tid][1] + sm.red_q[tid][2] + sm.red_q[tid][3];
            float mu  = s4 * (1.0f / U);
            float var = fmaxf(q4 * (1.0f / U) - mu * mu, 0.0f);
            sm.mu[tid] = mu;
            sm.rs[tid] = rsqrtf(var + LN_EPS_);
        }
        __syncthreads();
        sm.hn[gg][uu]     = sm.gm[uu] * (hA - sm.mu[gg])     * sm.rs[gg]     + sm.bt[uu];
        sm.hn[gg + 2][uu] = sm.gm[uu] * (hB - sm.mu[gg + 2]) * sm.rs[gg + 2] + sm.bt[uu];
        __syncthreads();

        // ---- prefetch next step's x/t into the other buffer ----
        if (t + 1 < TT) {
            int nb = buf ^ 1;
            if (tid < G) sm.tm[nb][tid] = times[(size_t)(bstart + tid) * TT + (t + 1)];
            if (tid < G * NF) {
                int g = tid / NF, f = tid - g * NF;
                sm.x[nb][g][f] = inputs[((size_t)(bstart + g) * TT + (t + 1)) * NF + f];
            }
        }

        // ================= layer 1: z = hn@Wx1 + h1@Wh1 + b1 =================
        if (ks == 0) {
            #pragma unroll
            for (int g = 0; g < G; ++g) {
                acc[g][0] = pack2(sm.b1[col + 0], sm.b1[col + 1]);
                acc[g][1] = pack2(sm.b1[col + 2], sm.b1[col + 3]);
            }
        } else {
            #pragma unroll
            for (int g = 0; g < G; ++g) { acc[g][0] = 0ull; acc[g][1] = 0ull; }
        }
        mv_accum(gWx1, &sm.hn[0][0], ks, col, acc);
        mv_accum(gWh1, &sm.h1[0][0], ks, col, acc);
        #pragma unroll
        for (int g = 0; g < G; ++g) {
            float2 p = unpack2(acc[g][0]), q = unpack2(acc[g][1]);
            *reinterpret_cast<float4*>(&sm.z[ks][g][col]) = make_float4(p.x, p.y, q.x, q.y);
        }
        __syncthreads();

        // ---- gates layer 1 ----
        float h1A = sm.h1[gg][uu],     c1A = sm.c1[gg][uu];
        float h1B = sm.h1[gg + 2][uu], c1B = sm.c1[gg + 2][uu];
        plstm_gate(&sm.z[0][gg][0],     &sm.z[1][gg][0],     uu, sm.tm[buf][gg],
                   sm.tau1[uu], sm.s1[uu], h1A, c1A);
        plstm_gate(&sm.z[0][gg + 2][0], &sm.z[1][gg + 2][0], uu, sm.tm[buf][gg + 2],
                   sm.tau1[uu], sm.s1[uu], h1B, c1B);
        sm.h1[gg][uu] = h1A;     sm.c1[gg][uu] = c1A;
        sm.h1[gg + 2][uu] = h1B; sm.c1[gg + 2][uu] = c1B;
        __syncthreads();

        // ================= output: softmax(h1 @ Wfc + bfc) =================
        if (tid < 160) {                       // 40 (g,c) pairs x 4 threads
            int pair = tid >> 2, sub = tid & 3;
            int g = pair / NC, c = pair - g * NC;
            float a = 0.0f;
            #pragma unroll
            for (int i = 0; i < 32; ++i) {
                int u = sub + 4 * i;
                a += sm.h1[g][u] * sm.Wfc[u * NC + c];
            }
            a += __shfl_xor_sync(0xffffffffu, a, 1);
            a += __shfl_xor_sync(0xffffffffu, a, 2);
            if (sub == 0) sm.logits[g][c] = a + sm.bfc[c];
        }
        __syncthreads();
        if (tid < G) {
            float mx = -1e30f;
            #pragma unroll
            for (int c = 0; c < NC; ++c) mx = fmaxf(mx, sm.logits[tid][c]);
            float e[NC]; float s = 0.0f;
            #pragma unroll
            for (int c = 0; c < NC; ++c) { e[c] = expf(sm.logits[tid][c] - mx); s += e[c]; }
            float inv = 1.0f / s;
            float* op = out + ((size_t)(bstart + tid) * TT + t) * NC;
            #pragma unroll
            for (int c = 0; c < NC; ++c) op[c] = e[c] * inv;
        }
        // No trailing barrier needed: every SMEM buffer written early in the next
        // iteration is separated from this iteration's readers by >=1 __syncthreads().
    }
}

extern "C" void kernel_launch(void* const* d_in, const int* in_sizes, int n_in,
                              void* d_out, int out_size) {
    const float* inputs = (const float*)d_in[0];
    const float* times  = (const float*)d_in[1];
    const float* Wx0    = (const float*)d_in[2];
    const float* Wh0    = (const float*)d_in[3];
    const float* b0     = (const float*)d_in[4];
    const float* tau0   = (const float*)d_in[5];
    const float* s0     = (const float*)d_in[6];
    const float* Wx1    = (const float*)d_in[7];
    const float* Wh1    = (const float*)d_in[8];
    const float* b1     = (const float*)d_in[9];
    const float* tau1   = (const float*)d_in[10];
    const float* s1     = (const float*)d_in[11];
    const float* gamma  = (const float*)d_in[12];
    const float* beta   = (const float*)d_in[13];
    const float* Wfc    = (const float*)d_in[14];
    const float* bfc    = (const float*)d_in[15];

    plstm_kernel<<<NBLK, NTHR>>>(inputs, times, Wx0, Wh0, b0, tau0, s0,
                                 Wx1, Wh1, b1, tau1, s1, gamma, beta,
                                 Wfc, bfc, (float*)d_out);
}

// round 7
// speedup vs baseline: 1.8303x; 1.8218x over previous
#include <cuda_runtime.h>
#include <math.h>
#include <stdint.h>

// Problem constants
#define U      128
#define NC     10
#define NF     3
#define TT     1000
#define BB     256
#define CSZ    4              // CTAs per cluster
#define GC     8              // batch elements per cluster
#define OWN    32             // units owned per CTA
#define NTHR   256
#define NCTA   128            // (BB/GC)*CSZ

#define R_ON_   0.05f
#define ALPHA_  0.001f
#define LN_EPS_ 1e-3f

// ---- packed f32x2 helpers (FFMA2: 2x fp32 MAC throughput) ----
__device__ __forceinline__ unsigned long long pack2(float a, float b) {
    unsigned long long r;
    asm("mov.b64 %0, {%1, %2};" : "=l"(r) : "f"(a), "f"(b));
    return r;
}
__device__ __forceinline__ float2 unpack2(unsigned long long v) {
    float2 r;
    asm("mov.b64 {%0, %1}, %2;" : "=f"(r.x), "=f"(r.y) : "l"(v));
    return r;
}
__device__ __forceinline__ void fma2p(unsigned long long& acc,
                                      unsigned long long a,
                                      unsigned long long b) {
    asm("fma.rn.f32x2 %0, %1, %2, %0;" : "+l"(acc) : "l"(a), "l"(b));
}

__device__ __forceinline__ float sigmoidf_(float x) { return 1.0f / (1.0f + expf(-x)); }

#define CLUSTER_SYNC() do { \
    asm volatile("barrier.cluster.arrive.aligned;" ::: "memory"); \
    asm volatile("barrier.cluster.wait.aligned;"   ::: "memory"); } while (0)

__device__ __forceinline__ void st_cluster_f32(uint32_t laddr, uint32_t r, float v) {
    uint32_t ra;
    asm volatile("mapa.shared::cluster.u32 %0, %1, %2;" : "=r"(ra) : "r"(laddr), "r"(r));
    asm volatile("st.shared::cluster.f32 [%0], %1;" :: "r"(ra), "f"(v) : "memory");
}
// store v to the same SMEM slot in all 4 cluster CTAs (incl. self)
__device__ __forceinline__ void bcast4_f32(void* p, float v) {
    uint32_t a = (uint32_t)__cvta_generic_to_shared(p);
    #pragma unroll
    for (uint32_t r = 0; r < CSZ; ++r) st_cluster_f32(a, r, v);
}

// Dynamic SMEM layout: 57952 floats = 231808 B  (<= 232448 B limit, 1 CTA/SM)
struct __align__(16) SM {
    float Wh0s[128 * 128];      // own 128 cols (gate-interleaved) of Wh0, [k][lc]
    float Wx1s[128 * 128];
    float Wh1s[128 * 128];
    float z[2 * 8 * 128];       // [ks][b][lc] gate pre-activation partials
    float h0f[2][128 * 8];      // full h0, [unit][b], double-buffered by t-parity
    float h1f[2][128 * 8];
    float h0l[GC * OWN], h1l[GC * OWN];  // own-unit state [b][j]
    float c0l[GC * OWN], c1l[GC * OWN];
    float Wx0s[NF * 128];       // own cols of Wx0 [f][lc]
    float b0s[128], b1s[128];   // own cols of biases
    float tau0s[OWN], s0s[OWN], tau1s[OWN], s1s[OWN];
    float gmf[128], btf[128];   // full gamma/beta
    float Wfcs[OWN * NC];       // own rows of Wfc
    float bfcs[16];
    float red_s[CSZ * GC], red_q[CSZ * GC];   // LN partials [srcRank][b]
    float lrecv[CSZ * 2 * 16];  // logit partials [srcRank][localBatch][c pad16]
    float xb[2][GC][4];         // double-buffered inputs (f padded to 4)
    float tmb[2][GC];           // double-buffered times
};

// One 64-row K-slab of  hf[128 units][8 b]  @  Ws[128][128 own cols], 1 col/thread.
// acc[p] = f32x2 over batches (2p, 2p+1).
__device__ __forceinline__ void mv_pass(const float* __restrict__ Ws,
                                        const float* __restrict__ hf,
                                        int kbase, int lc,
                                        unsigned long long acc[4]) {
    const float* w = Ws + kbase * 128 + lc;
    const float* h = hf + kbase * 8;
    #pragma unroll 8
    for (int k = 0; k < 64; ++k) {
        float wv = w[k * 128];
        unsigned long long wd = pack2(wv, wv);
        ulonglong2 hA = *reinterpret_cast<const ulonglong2*>(h + k * 8);      // b0..b3
        ulonglong2 hB = *reinterpret_cast<const ulonglong2*>(h + k * 8 + 4);  // b4..b7
        fma2p(acc[0], wd, hA.x);
        fma2p(acc[1], wd, hA.y);
        fma2p(acc[2], wd, hB.x);
        fma2p(acc[3], wd, hB.y);
    }
}

__device__ __forceinline__ void plstm_gate2(float zi, float zf, float zg, float zo,
                                            float tcur, float tau, float s,
                                            float& h, float& c) {
    float ch = sigmoidf_(zf) * c + sigmoidf_(zi) * tanhf(zg);
    float hh = sigmoidf_(zo) * tanhf(ch);
    float d = tcur - s;
    float m = fmodf(d, tau);
    if (m < 0.0f) m += tau;           // python-style mod (divisor > 0)
    float phi = m / tau;
    float kg;
    if (phi < 0.5f * R_ON_)      kg = 2.0f * phi / R_ON_;
    else if (phi < R_ON_)        kg = 2.0f - 2.0f * phi / R_ON_;
    else                         kg = ALPHA_ * phi;
    h = kg * hh + (1.0f - kg) * h;
    c = kg * ch + (1.0f - kg) * c;
}

__global__ void __launch_bounds__(NTHR, 1) __cluster_dims__(CSZ, 1, 1)
plstm_cluster_kernel(const float* __restrict__ inputs, const float* __restrict__ times,
                     const float* __restrict__ gWx0, const float* __restrict__ gWh0,
                     const float* __restrict__ gb0,  const float* __restrict__ gtau0,
                     const float* __restrict__ gs0,  const float* __restrict__ gWx1,
                     const float* __restrict__ gWh1, const float* __restrict__ gb1,
                     const float* __restrict__ gtau1,const float* __restrict__ gs1,
                     const float* __restrict__ ggamma,const float* __restrict__ gbeta,
                     const float* __restrict__ gWfc, const float* __restrict__ gbfc,
                     float* __restrict__ out) {
    extern __shared__ float smraw[];
    SM& sm = *reinterpret_cast<SM*>(smraw);
    const int tid = threadIdx.x;
    uint32_t rank;
    asm("mov.u32 %0, %%cluster_ctarank;" : "=r"(rank));
    const int bstart = (blockIdx.x >> 2) * GC;

    // ---- one-time SMEM setup: this CTA's column slabs (gate-interleaved) ----
    for (int i = tid; i < 128 * 128; i += NTHR) {
        int k = i >> 7, lc = i & 127;
        int gcol = ((lc >> 5) << 7) + ((int)rank << 5) + (lc & 31);
        sm.Wh0s[i] = gWh0[k * 512 + gcol];
        sm.Wx1s[i] = gWx1[k * 512 + gcol];
        sm.Wh1s[i] = gWh1[k * 512 + gcol];
    }
    for (int i = tid; i < NF * 128; i += NTHR) {
        int f = i >> 7, lc = i & 127;
        int gcol = ((lc >> 5) << 7) + ((int)rank << 5) + (lc & 31);
        sm.Wx0s[i] = gWx0[f * 512 + gcol];
    }
    for (int lc = tid; lc < 128; lc += NTHR) {
        int gcol = ((lc >> 5) << 7) + ((int)rank << 5) + (lc & 31);
        sm.b0s[lc] = gb0[gcol];
        sm.b1s[lc] = gb1[gcol];
        sm.gmf[lc] = ggamma[lc];
        sm.btf[lc] = gbeta[lc];
    }
    if (tid < OWN) {
        int u = (int)rank * OWN + tid;
        sm.tau0s[tid] = gtau0[u]; sm.s0s[tid] = gs0[u];
        sm.tau1s[tid] = gtau1[u]; sm.s1s[tid] = gs1[u];
    }
    for (int i = tid; i < OWN * NC; i += NTHR) {
        int j = i / NC, c2 = i - j * NC;
        sm.Wfcs[i] = gWfc[((int)rank * OWN + j) * NC + c2];
    }
    if (tid < NC) sm.bfcs[tid] = gbfc[tid];
    for (int i = tid; i < 128 * 8; i += NTHR) {
        sm.h0f[0][i] = 0.0f; sm.h0f[1][i] = 0.0f;
        sm.h1f[0][i] = 0.0f; sm.h1f[1][i] = 0.0f;
    }
    sm.h0l[tid] = 0.0f; sm.h1l[tid] = 0.0f;
    sm.c0l[tid] = 0.0f; sm.c1l[tid] = 0.0f;
    if (tid < GC) sm.tmb[0][tid] = times[(size_t)(bstart + tid) * TT];
    if (tid < GC * NF) {
        int g = tid / NF, f = tid - g * NF;
        sm.xb[0][g][f] = inputs[((size_t)(bstart + g) * TT) * NF + f];
    }
    __syncthreads();
    CLUSTER_SYNC();   // all CTAs' zero-init done before any remote writes land

    const int ks  = tid >> 7, lc = tid & 127, kbase = ks << 6;  // matvec mapping
    const int gb  = tid >> 5, gj = tid & 31;                    // gate mapping (warp gb = batch gb)
    const int hk  = tid >> 1, hb4 = (tid & 1) << 2;             // hn mapping

    for (int t = 0; t < TT; ++t) {
        const int par = t & 1, parn = par ^ 1;

        // ============ layer 0 matvec: z0 = x@Wx0 + h0@Wh0 + b0 (own cols) ============
        unsigned long long acc[4];
        if (ks == 0) {
            float w0 = sm.Wx0s[lc], w1 = sm.Wx0s[128 + lc], w2 = sm.Wx0s[256 + lc];
            float bz = sm.b0s[lc];
            #pragma unroll
            for (int p = 0; p < 4; ++p) {
                const float* xl = sm.xb[par][2 * p];
                const float* xh = sm.xb[par][2 * p + 1];
                float alo = bz + xl[0] * w0 + xl[1] * w1 + xl[2] * w2;
                float ahi = bz + xh[0] * w0 + xh[1] * w1 + xh[2] * w2;
                acc[p] = pack2(alo, ahi);
            }
        } else {
            #pragma unroll
            for (int p = 0; p < 4; ++p) acc[p] = 0ull;
        }
        mv_pass(sm.Wh0s, sm.h0f[par], kbase, lc, acc);
        #pragma unroll
        for (int p = 0; p < 4; ++p) {
            float2 v = unpack2(acc[p]);
            sm.z[(ks * 8 + 2 * p) * 128 + lc]     = v.x;
            sm.z[(ks * 8 + 2 * p + 1) * 128 + lc] = v.y;
        }
        // prefetch next step's x/t
        if (t + 1 < TT) {
            if (tid < GC) sm.tmb[parn][tid] = times[(size_t)(bstart + tid) * TT + t + 1];
            if (tid < GC * NF) {
                int g = tid / NF, f = tid - g * NF;
                sm.xb[parn][g][f] = inputs[((size_t)(bstart + g) * TT + t + 1) * NF + f];
            }
        }
        __syncthreads();                           // B1: z0 ready

        // ============ layer 0 gates (own units) + h0 exchange + LN partials ============
        {
            const float* zb = sm.z + gb * 128;
            float zi = zb[gj]          + zb[1024 + gj];
            float zf = zb[32 + gj]     + zb[1024 + 32 + gj];
            float zg = zb[64 + gj]     + zb[1024 + 64 + gj];
            float zo = zb[96 + gj]     + zb[1024 + 96 + gj];
            float h = sm.h0l[gb * OWN + gj], c = sm.c0l[gb * OWN + gj];
            plstm_gate2(zi, zf, zg, zo, sm.tmb[par][gb], sm.tau0s[gj], sm.s0s[gj], h, c);
            sm.h0l[gb * OWN + gj] = h; sm.c0l[gb * OWN + gj] = c;
            int u = (int)rank * OWN + gj;
            bcast4_f32(&sm.h0f[parn][u * 8 + gb], h);
            float s = h, q = h * h;
            #pragma unroll
            for (int o = 16; o; o >>= 1) {
                s += __shfl_xor_sync(0xffffffffu, s, o);
                q += __shfl_xor_sync(0xffffffffu, q, o);
            }
            if (gj == 0) {
                bcast4_f32(&sm.red_s[rank * GC + gb], s);
                bcast4_f32(&sm.red_q[rank * GC + gb], q);
            }
        }
        CLUSTER_SYNC();                            // S1: h0f[parn] + LN partials visible

        // ============ LayerNorm -> hn (redundant per CTA; hn aliases h0f[par]) ============
        {
            float mu[4], rs[4];
            #pragma unroll
            for (int q = 0; q < 4; ++q) {
                int b = hb4 + q;
                float s  = sm.red_s[b] + sm.red_s[8 + b] + sm.red_s[16 + b] + sm.red_s[24 + b];
                float sq = sm.red_q[b] + sm.red_q[8 + b] + sm.red_q[16 + b] + sm.red_q[24 + b];
                float m = s * (1.0f / 128.0f);
                float v = fmaxf(sq * (1.0f / 128.0f) - m * m, 0.0f);
                mu[q] = m; rs[q] = rsqrtf(v + LN_EPS_);
            }
            float4 hv = *reinterpret_cast<const float4*>(&sm.h0f[parn][hk * 8 + hb4]);
            float gm = sm.gmf[hk], bt = sm.btf[hk];
            float4 hn;
            hn.x = gm * (hv.x - mu[0]) * rs[0] + bt;
            hn.y = gm * (hv.y - mu[1]) * rs[1] + bt;
            hn.z = gm * (hv.z - mu[2]) * rs[2] + bt;
            hn.w = gm * (hv.w - mu[3]) * rs[3] + bt;
            *reinterpret_cast<float4*>(&sm.h0f[par][hk * 8 + hb4]) = hn;
        }
        __syncthreads();                           // B2: hn ready

        // ============ layer 1 matvec: z1 = hn@Wx1 + h1@Wh1 + b1 (own cols) ============
        if (ks == 0) {
            float bz = sm.b1s[lc];
            #pragma unroll
            for (int p = 0; p < 4; ++p) acc[p] = pack2(bz, bz);
        } else {
            #pragma unroll
            for (int p = 0; p < 4; ++p) acc[p] = 0ull;
        }
        mv_pass(sm.Wx1s, sm.h0f[par], kbase, lc, acc);   // hn lives in h0f[par]
        mv_pass(sm.Wh1s, sm.h1f[par], kbase, lc, acc);
        #pragma unroll
        for (int p = 0; p < 4; ++p) {
            float2 v = unpack2(acc[p]);
            sm.z[(ks * 8 + 2 * p) * 128 + lc]     = v.x;
            sm.z[(ks * 8 + 2 * p + 1) * 128 + lc] = v.y;
        }
        __syncthreads();                           // B3: z1 ready

        // ============ layer 1 gates (own units) + h1 exchange ============
        {
            const float* zb = sm.z + gb * 128;
            float zi = zb[gj]          + zb[1024 + gj];
            float zf = zb[32 + gj]     + zb[1024 + 32 + gj];
            float zg = zb[64 + gj]     + zb[1024 + 64 + gj];
            float zo = zb[96 + gj]     + zb[1024 + 96 + gj];
            float h = sm.h1l[gb * OWN + gj], c = sm.c1l[gb * OWN + gj];
            plstm_gate2(zi, zf, zg, zo, sm.tmb[par][gb], sm.tau1s[gj], sm.s1s[gj], h, c);
            sm.h1l[gb * OWN + gj] = h; sm.c1l[gb * OWN + gj] = c;
            int u = (int)rank * OWN + gj;
            bcast4_f32(&sm.h1f[parn][u * 8 + gb], h);
        }
        __syncthreads();                           // B4: h1l ready for FC

        // ============ FC partials over own 32 units -> owner rank ============
        if (tid < 80) {
            int fb = tid / 10, fc = tid - fb * 10;
            float a = 0.0f;
            #pragma unroll
            for (int jj = 0; jj < OWN; ++jj)
                a += sm.h1l[fb * OWN + jj] * sm.Wfcs[jj * NC + fc];
            int owner = fb >> 1, bL = fb & 1;
            uint32_t ad = (uint32_t)__cvta_generic_to_shared(
                &sm.lrecv[((int)rank * 2 + bL) * 16 + fc]);
            st_cluster_f32(ad, (uint32_t)owner, a);
        }
        CLUSTER_SYNC();                            // S2: h1f[parn] + logit partials visible

        // ============ softmax + output for this CTA's 2 batches ============
        if (tid < 2) {
            float lg[NC], mx = -1e30f;
            #pragma unroll
            for (int c2 = 0; c2 < NC; ++c2) {
                float v = sm.bfcs[c2]
                        + sm.lrecv[(0 + tid) * 16 + c2] + sm.lrecv[(2 + tid) * 16 + c2]
                        + sm.lrecv[(4 + tid) * 16 + c2] + sm.lrecv[(6 + tid) * 16 + c2];
                lg[c2] = v; mx = fmaxf(mx, v);
            }
            float e[NC], ssum = 0.0f;
            #pragma unroll
            for (int c2 = 0; c2 < NC; ++c2) { e[c2] = expf(lg[c2] - mx); ssum += e[c2]; }
            float inv = 1.0f / ssum;
            float* op = out + ((size_t)(bstart + (int)rank * 2 + tid) * TT + t) * NC;
            #pragma unroll
            for (int c2 = 0; c2 < NC; ++c2) op[c2] = e[c2] * inv;
        }
        // next iteration's first SMEM writes (z) happen only after all threads passed S2
    }
}

extern "C" void kernel_launch(void* const* d_in, const int* in_sizes, int n_in,
                              void* d_out, int out_size) {
    const float* inputs = (const float*)d_in[0];
    const float* times  = (const float*)d_in[1];
    const float* Wx0    = (const float*)d_in[2];
    const float* Wh0    = (const float*)d_in[3];
    const float* b0     = (const float*)d_in[4];
    const float* tau0   = (const float*)d_in[5];
    const float* s0     = (const float*)d_in[6];
    const float* Wx1    = (const float*)d_in[7];
    const float* Wh1    = (const float*)d_in[8];
    const float* b1     = (const float*)d_in[9];
    const float* tau1   = (const float*)d_in[10];
    const float* s1     = (const float*)d_in[11];
    const float* gamma  = (const float*)d_in[12];
    const float* beta   = (const float*)d_in[13];
    const float* Wfc    = (const float*)d_in[14];
    const float* bfc    = (const float*)d_in[15];

    cudaFuncSetAttribute(plstm_cluster_kernel,
                         cudaFuncAttributeMaxDynamicSharedMemorySize,
                         (int)sizeof(SM));
    plstm_cluster_kernel<<<NCTA, NTHR, sizeof(SM)>>>(
        inputs, times, Wx0, Wh0, b0, tau0, s0,
        Wx1, Wh1, b1, tau1, s1, gamma, beta, Wfc, bfc, (float*)d_out);
}